// round 3
// baseline (speedup 1.0000x reference)
#include <cuda_runtime.h>
#include <cuda_bf16.h>
#include <math.h>

#define BB 16
#define NN 512
#define DD 256
#define LL 4
#define HH 8
#define DK 32
#define DFF 1024

// ------------------------- scratch (device globals) -------------------------
__device__ float g_x[BB * NN * DD];
__device__ float g_xv[BB * NN * DD];
__device__ float g_q[BB * NN * DD];
__device__ float g_k[BB * NN * DD];
__device__ float g_v[BB * NN * DD];
__device__ float g_ao[BB * NN * DD];   // attention output (pre-Wo)
__device__ float g_o[BB * NN * DD];    // after Wo
__device__ float g_h[BB * NN * DFF];   // FFN hidden
__device__ float g_h2[BB * NN * DD];   // FFN output

// ------------------------- add positional embedding -------------------------
__global__ void add_pos_kernel(const float* __restrict__ in,
                               const float* __restrict__ in_v,
                               const float* __restrict__ pos,
                               float* __restrict__ x, float* __restrict__ xv) {
    size_t i = (size_t)blockIdx.x * 256 + threadIdx.x;
    float p = pos[i % (NN * DD)];
    x[i]  = in[i]  + p;
    xv[i] = in_v[i] + p;
}

// ------------------------- tiled GEMM + bias (+gelu) -------------------------
// C[M,Nc] = A[M,K] @ W[K,Nc] + bias[Nc]; all dims multiples of tile sizes.
#define TBM 64
#define TBN 64
#define TBK 16
__global__ void gemm_bias_kernel(const float* __restrict__ A,
                                 const float* __restrict__ W,
                                 const float* __restrict__ bias,
                                 float* __restrict__ C,
                                 int M, int K, int Nc, int apply_gelu) {
    __shared__ float As[TBK][TBM];
    __shared__ float Bs[TBK][TBN];
    const int tx = threadIdx.x, ty = threadIdx.y;
    const int tid = ty * 16 + tx;
    const int row0 = blockIdx.y * TBM;
    const int col0 = blockIdx.x * TBN;

    float acc[4][4] = {};

    for (int k0 = 0; k0 < K; k0 += TBK) {
        // A tile: 64 rows x 16 k
#pragma unroll
        for (int j = 0; j < 4; j++) {
            int e = tid + j * 256;
            int r = e >> 4, c = e & 15;
            As[c][r] = A[(size_t)(row0 + r) * K + k0 + c];
        }
        // W tile: 16 k x 64 cols
#pragma unroll
        for (int j = 0; j < 4; j++) {
            int e = tid + j * 256;
            int r = e >> 6, c = e & 63;
            Bs[r][c] = W[(size_t)(k0 + r) * Nc + col0 + c];
        }
        __syncthreads();
#pragma unroll
        for (int kk = 0; kk < TBK; kk++) {
            float a[4], b[4];
#pragma unroll
            for (int i = 0; i < 4; i++) a[i] = As[kk][ty + 16 * i];
#pragma unroll
            for (int j = 0; j < 4; j++) b[j] = Bs[kk][tx + 16 * j];
#pragma unroll
            for (int i = 0; i < 4; i++)
#pragma unroll
                for (int j = 0; j < 4; j++)
                    acc[i][j] += a[i] * b[j];
        }
        __syncthreads();
    }

#pragma unroll
    for (int i = 0; i < 4; i++) {
        int r = row0 + ty + 16 * i;
#pragma unroll
        for (int j = 0; j < 4; j++) {
            int c = col0 + tx + 16 * j;
            float v = acc[i][j] + bias[c];
            if (apply_gelu) {
                v = 0.5f * v * (1.0f + erff(v * 0.70710678118654752f));
            }
            C[(size_t)r * Nc + c] = v;
        }
    }
}

// ------------------------- fused attention -------------------------
// grid: (N/16, H, B), block: 256.  Scores for a 16-query tile kept in smem.
// mask is read as 32-bit words (harness widens bool to int32 or float32;
// nonzero word == True either way).
__global__ void attn_kernel(const float* __restrict__ q,
                            const float* __restrict__ k,
                            const float* __restrict__ v,
                            const int* __restrict__ mask,
                            float* __restrict__ out, int use_mask) {
    const int b = blockIdx.z, h = blockIdx.y, q0 = blockIdx.x * 16;
    __shared__ float Qs[16][33];
    __shared__ float Ks[64][33];
    __shared__ float S[16][512];
    const int tid = threadIdx.x;
    const float scale = 0.17677669529663687f;  // 1/sqrt(32)

    // load Q tile
    for (int e = tid; e < 16 * 32; e += 256) {
        int r = e >> 5, d = e & 31;
        Qs[r][d] = q[(size_t)(b * NN + q0 + r) * DD + h * DK + d];
    }

    // scores
    for (int kc = 0; kc < NN; kc += 64) {
        __syncthreads();
        for (int e = tid; e < 64 * 32; e += 256) {
            int r = e >> 5, d = e & 31;
            Ks[r][d] = k[(size_t)(b * NN + kc + r) * DD + h * DK + d];
        }
        __syncthreads();
        for (int e = tid; e < 16 * 64; e += 256) {
            int r = e >> 6, c = e & 63;
            float dot = 0.0f;
#pragma unroll
            for (int d = 0; d < DK; d++) dot += Qs[r][d] * Ks[c][d];
            float s = dot * scale;
            if (use_mask && mask[(size_t)(q0 + r) * NN + kc + c] != 0) s = -1e30f;
            S[r][kc + c] = s;
        }
    }
    __syncthreads();

    // softmax: 8 warps, 2 rows each
    const int warp = tid >> 5, lane = tid & 31;
    for (int r = warp; r < 16; r += 8) {
        float mx = -1e30f;
        for (int c = lane; c < NN; c += 32) mx = fmaxf(mx, S[r][c]);
#pragma unroll
        for (int o = 16; o; o >>= 1) mx = fmaxf(mx, __shfl_xor_sync(0xFFFFFFFFu, mx, o));
        float sum = 0.0f;
        for (int c = lane; c < NN; c += 32) {
            float e = __expf(S[r][c] - mx);
            S[r][c] = e;
            sum += e;
        }
#pragma unroll
        for (int o = 16; o; o >>= 1) sum += __shfl_xor_sync(0xFFFFFFFFu, sum, o);
        float inv = 1.0f / sum;
        for (int c = lane; c < NN; c += 32) S[r][c] *= inv;
    }
    __syncthreads();

    // O = P @ V.  thread (warp=r1, lane=d); also handles r2=r1+8. V load shared
    // between the two rows (same k,d).
    {
        int d = tid & 31;
        int r1 = tid >> 5;
        int r2 = r1 + 8;
        float acc1 = 0.0f, acc2 = 0.0f;
        const float* vb = v + (size_t)b * NN * DD + h * DK + d;
#pragma unroll 4
        for (int kk = 0; kk < NN; kk++) {
            float vv = vb[(size_t)kk * DD];
            acc1 += S[r1][kk] * vv;
            acc2 += S[r2][kk] * vv;
        }
        out[(size_t)(b * NN + q0 + r1) * DD + h * DK + d] = acc1;
        out[(size_t)(b * NN + q0 + r2) * DD + h * DK + d] = acc2;
    }
}

// ------------------------- residual + layernorm -------------------------
// grid: B*N rows, block: 256 (= D). out = LN(x + res) * g + b
__global__ void ln_kernel(const float* __restrict__ x,
                          const float* __restrict__ res,
                          const float* __restrict__ g,
                          const float* __restrict__ bta,
                          float* __restrict__ out) {
    const int row = blockIdx.x;
    const int i = threadIdx.x;
    __shared__ float red[256];
    size_t base = (size_t)row * DD;
    float val = x[base + i] + (res ? res[base + i] : 0.0f);
    red[i] = val;
    __syncthreads();
    for (int s = 128; s; s >>= 1) {
        if (i < s) red[i] += red[i + s];
        __syncthreads();
    }
    float mean = red[0] * (1.0f / DD);
    __syncthreads();
    float dv = val - mean;
    red[i] = dv * dv;
    __syncthreads();
    for (int s = 128; s; s >>= 1) {
        if (i < s) red[i] += red[i + s];
        __syncthreads();
    }
    float var = red[0] * (1.0f / DD);
    out[base + i] = dv * rsqrtf(var + 1e-5f) * g[i] + bta[i];
}

// ------------------------- launch -------------------------
extern "C" void kernel_launch(void* const* d_in, const int* in_sizes, int n_in,
                              void* d_out, int out_size) {
    const float* input   = (const float*)d_in[0];
    const float* input_v = (const float*)d_in[1];
    const float* pos_emb = (const float*)d_in[2];
    const float* Wq = (const float*)d_in[3];
    const float* bq = (const float*)d_in[4];
    const float* Wk = (const float*)d_in[5];
    const float* bk = (const float*)d_in[6];
    const float* Wv = (const float*)d_in[7];
    const float* bv = (const float*)d_in[8];
    const float* Wo = (const float*)d_in[9];
    const float* bo = (const float*)d_in[10];
    const float* W1 = (const float*)d_in[11];
    const float* b1 = (const float*)d_in[12];
    const float* W2 = (const float*)d_in[13];
    const float* b2 = (const float*)d_in[14];
    const float* g1 = (const float*)d_in[15];
    const float* be1 = (const float*)d_in[16];
    const float* g2 = (const float*)d_in[17];
    const float* be2 = (const float*)d_in[18];
    const float* gf = (const float*)d_in[19];
    const float* bf = (const float*)d_in[20];
    const int* mask = (const int*)d_in[21];

    float *x, *xv, *q, *k, *v, *ao, *o, *h, *h2;
    cudaGetSymbolAddress((void**)&x, g_x);
    cudaGetSymbolAddress((void**)&xv, g_xv);
    cudaGetSymbolAddress((void**)&q, g_q);
    cudaGetSymbolAddress((void**)&k, g_k);
    cudaGetSymbolAddress((void**)&v, g_v);
    cudaGetSymbolAddress((void**)&ao, g_ao);
    cudaGetSymbolAddress((void**)&o, g_o);
    cudaGetSymbolAddress((void**)&h, g_h);
    cudaGetSymbolAddress((void**)&h2, g_h2);

    const int M = BB * NN;  // 8192

    add_pos_kernel<<<(BB * NN * DD) / 256, 256>>>(input, input_v, pos_emb, x, xv);

    dim3 tb(16, 16);
    for (int i = 0; i < LL; i++) {
        const float* Wqi = Wq + (size_t)i * DD * DD;
        const float* Wki = Wk + (size_t)i * DD * DD;
        const float* Wvi = Wv + (size_t)i * DD * DD;
        const float* Woi = Wo + (size_t)i * DD * DD;
        const float* W1i = W1 + (size_t)i * DD * DFF;
        const float* W2i = W2 + (size_t)i * (DFF / 2) * (DD / 2);

        // QKV projections
        gemm_bias_kernel<<<dim3(DD / TBN, M / TBM), tb>>>(x,  Wqi, bq + i * DD, q, M, DD, DD, 0);
        gemm_bias_kernel<<<dim3(DD / TBN, M / TBM), tb>>>(x,  Wki, bk + i * DD, k, M, DD, DD, 0);
        gemm_bias_kernel<<<dim3(DD / TBN, M / TBM), tb>>>(xv, Wvi, bv + i * DD, v, M, DD, DD, 0);

        // attention
        attn_kernel<<<dim3(NN / 16, HH, BB), 256>>>(q, k, v, mask, ao, (i % 2) ? 1 : 0);

        // output projection
        gemm_bias_kernel<<<dim3(DD / TBN, M / TBM), tb>>>(ao, Woi, bo + i * DD, o, M, DD, DD, 0);

        // x = LN(x + o)
        ln_kernel<<<M, 256>>>(x, o, g1 + i * DD, be1 + i * DD, x);

        // FFN1 + GELU
        gemm_bias_kernel<<<dim3(DFF / TBN, M / TBM), tb>>>(x, W1i, b1 + i * DFF, h, M, DD, DFF, 1);

        // FFN2 grouped: (B*N*2, 512) @ (512, 128) -> contiguous (B*N, 256)
        gemm_bias_kernel<<<dim3((DD / 2) / TBN, (2 * M) / TBM), tb>>>(
            h, W2i, b2 + i * (DD / 2), h2, 2 * M, DFF / 2, DD / 2, 0);

        // x = LN(x + h2)
        ln_kernel<<<M, 256>>>(x, h2, g2 + i * DD, be2 + i * DD, x);
    }

    // final LN -> output
    ln_kernel<<<M, 256>>>(x, nullptr, gf, bf, (float*)d_out);
}

// round 5
// speedup vs baseline: 1.1013x; 1.1013x over previous
#include <cuda_runtime.h>
#include <cuda_bf16.h>
#include <math.h>

#define BB 16
#define NN 512
#define DD 256
#define LL 4
#define HH 8
#define DK 32
#define DFF 1024

// ------------------------- scratch (device globals) -------------------------
__device__ float g_x[BB * NN * DD];
__device__ float g_xv[BB * NN * DD];
__device__ float g_q[BB * NN * DD];
__device__ float g_k[BB * NN * DD];
__device__ float g_v[BB * NN * DD];
__device__ float g_ao[BB * NN * DD];
__device__ float g_o[BB * NN * DD];
__device__ float g_h[BB * NN * DFF];
__device__ float g_h2[BB * NN * DD];

// ------------------------- add positional embedding -------------------------
__global__ void add_pos_kernel(const float* __restrict__ in,
                               const float* __restrict__ in_v,
                               const float* __restrict__ pos,
                               float* __restrict__ x, float* __restrict__ xv) {
    size_t i = (size_t)blockIdx.x * 256 + threadIdx.x;
    float p = pos[i % (NN * DD)];
    x[i]  = in[i]  + p;
    xv[i] = in_v[i] + p;
}

// ------------------- 128x128x8 double-buffered GEMM + bias (+gelu) ----------
// C[M,Nc] = A[M,K] @ W[K,Nc] + bias[Nc].  M%128==0, Nc%128==0, K%8==0.
#define GM 128
#define GN 128
#define GKK 8

__global__ __launch_bounds__(256, 2)
void gemm128_kernel(const float* __restrict__ A,
                    const float* __restrict__ W,
                    const float* __restrict__ bias,
                    float* __restrict__ C,
                    int M, int K, int Nc, int apply_gelu) {
    __shared__ float As[2][GKK][GM];
    __shared__ float Bs[2][GKK][GN];
    const int tid = threadIdx.x;
    const int tx = tid & 15, ty = tid >> 4;
    const int row0 = blockIdx.y * GM, col0 = blockIdx.x * GN;

    // A ldg: one float4 per thread: row = tid>>1, k quad = (tid&1)*4
    const int arow = tid >> 1, ak0 = (tid & 1) * 4;
    // B ldg: one float4 per thread: k row = tid>>5, col quad = (tid&31)*4
    const int brow = tid >> 5, bcol = (tid & 31) * 4;

    const float* Aptr = A + (size_t)(row0 + arow) * K + ak0;
    const float* Wptr = W + (size_t)brow * Nc + col0 + bcol;

    // prologue: tile 0
    {
        float4 a4 = *(const float4*)Aptr;
        float4 b4 = *(const float4*)Wptr;
        As[0][ak0 + 0][arow] = a4.x;
        As[0][ak0 + 1][arow] = a4.y;
        As[0][ak0 + 2][arow] = a4.z;
        As[0][ak0 + 3][arow] = a4.w;
        *(float4*)&Bs[0][brow][bcol] = b4;
    }
    __syncthreads();

    float acc[8][8];
#pragma unroll
    for (int i = 0; i < 8; i++)
#pragma unroll
        for (int j = 0; j < 8; j++) acc[i][j] = 0.0f;

    int buf = 0;
    for (int k0 = 0; k0 < K; k0 += GKK) {
        const bool has_next = (k0 + GKK < K);
        float4 na, nb;
        if (has_next) {
            na = *(const float4*)(Aptr + k0 + GKK);
            nb = *(const float4*)(Wptr + (size_t)(k0 + GKK) * Nc);
        }
#pragma unroll
        for (int kk = 0; kk < GKK; kk++) {
            float a[8], b[8];
            *(float4*)(a)     = *(const float4*)&As[buf][kk][ty * 4];
            *(float4*)(a + 4) = *(const float4*)&As[buf][kk][64 + ty * 4];
            *(float4*)(b)     = *(const float4*)&Bs[buf][kk][tx * 4];
            *(float4*)(b + 4) = *(const float4*)&Bs[buf][kk][64 + tx * 4];
#pragma unroll
            for (int i = 0; i < 8; i++)
#pragma unroll
                for (int j = 0; j < 8; j++)
                    acc[i][j] += a[i] * b[j];
        }
        if (has_next) {
            As[buf ^ 1][ak0 + 0][arow] = na.x;
            As[buf ^ 1][ak0 + 1][arow] = na.y;
            As[buf ^ 1][ak0 + 2][arow] = na.z;
            As[buf ^ 1][ak0 + 3][arow] = na.w;
            *(float4*)&Bs[buf ^ 1][brow][bcol] = nb;
            __syncthreads();
            buf ^= 1;
        }
    }

    // epilogue: bias (+gelu), float4 stores
    const int c0 = col0 + tx * 4;
    const int c1 = col0 + 64 + tx * 4;
    float4 bia0 = *(const float4*)&bias[c0];
    float4 bia1 = *(const float4*)&bias[c1];
#pragma unroll
    for (int i = 0; i < 8; i++) {
        int r = row0 + (i < 4 ? ty * 4 + i : 64 + ty * 4 + (i - 4));
        float o0[4] = {acc[i][0] + bia0.x, acc[i][1] + bia0.y,
                       acc[i][2] + bia0.z, acc[i][3] + bia0.w};
        float o1[4] = {acc[i][4] + bia1.x, acc[i][5] + bia1.y,
                       acc[i][6] + bia1.z, acc[i][7] + bia1.w};
        if (apply_gelu) {
#pragma unroll
            for (int j = 0; j < 4; j++) {
                o0[j] = 0.5f * o0[j] * (1.0f + erff(o0[j] * 0.70710678118654752f));
                o1[j] = 0.5f * o1[j] * (1.0f + erff(o1[j] * 0.70710678118654752f));
            }
        }
        *(float4*)&C[(size_t)r * Nc + c0] = *(float4*)o0;
        *(float4*)&C[(size_t)r * Nc + c1] = *(float4*)o1;
    }
}

// ------------------------- fused attention -------------------------
// grid: (N/16, H, B), block: 256.  Scores for a 16-query tile kept in smem.
// mask read as 32-bit words (nonzero == True).
__global__ void attn_kernel(const float* __restrict__ q,
                            const float* __restrict__ k,
                            const float* __restrict__ v,
                            const int* __restrict__ mask,
                            float* __restrict__ out, int use_mask) {
    const int b = blockIdx.z, h = blockIdx.y, q0 = blockIdx.x * 16;
    __shared__ float Qs[16][33];
    __shared__ float Kt[32][68];    // transposed K chunk: [d][key]
    __shared__ float S[16][512];
    const int tid = threadIdx.x;
    const float scale = 0.17677669529663687f;  // 1/sqrt(32)

    // load Q tile
    for (int e = tid; e < 16 * 32; e += 256) {
        int r = e >> 5, d = e & 31;
        Qs[r][d] = q[(size_t)(b * NN + q0 + r) * DD + h * DK + d];
    }

    // scores: thread handles row r = tid>>4, cols cg*4..cg*4+3
    const int sr = tid >> 4;
    const int scg = tid & 15;
    for (int kc = 0; kc < NN; kc += 64) {
        __syncthreads();
        for (int e = tid; e < 64 * 32; e += 256) {
            int rr = e >> 5, d = e & 31;
            Kt[d][rr] = k[(size_t)(b * NN + kc + rr) * DD + h * DK + d];
        }
        __syncthreads();
        float a0 = 0.0f, a1 = 0.0f, a2 = 0.0f, a3 = 0.0f;
#pragma unroll
        for (int d = 0; d < DK; d++) {
            float qv = Qs[sr][d];
            float4 kv = *(const float4*)&Kt[d][scg * 4];
            a0 += qv * kv.x;
            a1 += qv * kv.y;
            a2 += qv * kv.z;
            a3 += qv * kv.w;
        }
        float s0 = a0 * scale, s1 = a1 * scale, s2 = a2 * scale, s3 = a3 * scale;
        if (use_mask) {
            const int* mp = &mask[(size_t)(q0 + sr) * NN + kc + scg * 4];
            int4 m4 = *(const int4*)mp;
            if (m4.x) s0 = -1e30f;
            if (m4.y) s1 = -1e30f;
            if (m4.z) s2 = -1e30f;
            if (m4.w) s3 = -1e30f;
        }
        float4 sv = make_float4(s0, s1, s2, s3);
        *(float4*)&S[sr][kc + scg * 4] = sv;
    }
    __syncthreads();

    // softmax: 8 warps, 2 rows each
    const int warp = tid >> 5, lane = tid & 31;
    for (int r = warp; r < 16; r += 8) {
        float mx = -1e30f;
        for (int c = lane; c < NN; c += 32) mx = fmaxf(mx, S[r][c]);
#pragma unroll
        for (int o = 16; o; o >>= 1) mx = fmaxf(mx, __shfl_xor_sync(0xFFFFFFFFu, mx, o));
        float sum = 0.0f;
        for (int c = lane; c < NN; c += 32) {
            float e = __expf(S[r][c] - mx);
            S[r][c] = e;
            sum += e;
        }
#pragma unroll
        for (int o = 16; o; o >>= 1) sum += __shfl_xor_sync(0xFFFFFFFFu, sum, o);
        float inv = 1.0f / sum;
        for (int c = lane; c < NN; c += 32) S[r][c] *= inv;
    }
    __syncthreads();

    // O = P @ V.  thread (warp=r1, lane=d); also r2=r1+8.
    {
        int d = tid & 31;
        int r1 = tid >> 5;
        int r2 = r1 + 8;
        float acc1 = 0.0f, acc2 = 0.0f;
        const float* vb = v + (size_t)b * NN * DD + h * DK + d;
#pragma unroll 4
        for (int kk = 0; kk < NN; kk++) {
            float vv = vb[(size_t)kk * DD];
            acc1 += S[r1][kk] * vv;
            acc2 += S[r2][kk] * vv;
        }
        out[(size_t)(b * NN + q0 + r1) * DD + h * DK + d] = acc1;
        out[(size_t)(b * NN + q0 + r2) * DD + h * DK + d] = acc2;
    }
}

// ------------------------- residual + layernorm -------------------------
// grid: B*N rows, block: 256 (= D). out = LN(x + res) * g + b
__global__ void ln_kernel(const float* __restrict__ x,
                          const float* __restrict__ res,
                          const float* __restrict__ g,
                          const float* __restrict__ bta,
                          float* __restrict__ out) {
    const int row = blockIdx.x;
    const int i = threadIdx.x;
    const int warp = i >> 5, lane = i & 31;
    __shared__ float ps[8], ps2[8];
    size_t base = (size_t)row * DD;
    float val = x[base + i] + (res ? res[base + i] : 0.0f);
    float s = val, s2 = val * val;
#pragma unroll
    for (int o = 16; o; o >>= 1) {
        s  += __shfl_xor_sync(0xFFFFFFFFu, s, o);
        s2 += __shfl_xor_sync(0xFFFFFFFFu, s2, o);
    }
    if (lane == 0) { ps[warp] = s; ps2[warp] = s2; }
    __syncthreads();
    if (warp == 0) {
        float a = ps[lane & 7], a2 = ps2[lane & 7];
#pragma unroll
        for (int o = 4; o; o >>= 1) {
            a  += __shfl_xor_sync(0xFFFFFFFFu, a, o);
            a2 += __shfl_xor_sync(0xFFFFFFFFu, a2, o);
        }
        if (lane == 0) { ps[0] = a; ps2[0] = a2; }
    }
    __syncthreads();
    float mean = ps[0] * (1.0f / DD);
    float var = ps2[0] * (1.0f / DD) - mean * mean;
    out[base + i] = (val - mean) * rsqrtf(var + 1e-5f) * g[i] + bta[i];
}

// ------------------------- launch -------------------------
extern "C" void kernel_launch(void* const* d_in, const int* in_sizes, int n_in,
                              void* d_out, int out_size) {
    const float* input   = (const float*)d_in[0];
    const float* input_v = (const float*)d_in[1];
    const float* pos_emb = (const float*)d_in[2];
    const float* Wq = (const float*)d_in[3];
    const float* bq = (const float*)d_in[4];
    const float* Wk = (const float*)d_in[5];
    const float* bk = (const float*)d_in[6];
    const float* Wv = (const float*)d_in[7];
    const float* bv = (const float*)d_in[8];
    const float* Wo = (const float*)d_in[9];
    const float* bo = (const float*)d_in[10];
    const float* W1 = (const float*)d_in[11];
    const float* b1 = (const float*)d_in[12];
    const float* W2 = (const float*)d_in[13];
    const float* b2 = (const float*)d_in[14];
    const float* g1 = (const float*)d_in[15];
    const float* be1 = (const float*)d_in[16];
    const float* g2 = (const float*)d_in[17];
    const float* be2 = (const float*)d_in[18];
    const float* gf = (const float*)d_in[19];
    const float* bf = (const float*)d_in[20];
    const int* mask = (const int*)d_in[21];

    float *x, *xv, *q, *k, *v, *ao, *o, *h, *h2;
    cudaGetSymbolAddress((void**)&x, g_x);
    cudaGetSymbolAddress((void**)&xv, g_xv);
    cudaGetSymbolAddress((void**)&q, g_q);
    cudaGetSymbolAddress((void**)&k, g_k);
    cudaGetSymbolAddress((void**)&v, g_v);
    cudaGetSymbolAddress((void**)&ao, g_ao);
    cudaGetSymbolAddress((void**)&o, g_o);
    cudaGetSymbolAddress((void**)&h, g_h);
    cudaGetSymbolAddress((void**)&h2, g_h2);

    const int M = BB * NN;  // 8192

    add_pos_kernel<<<(BB * NN * DD) / 256, 256>>>(input, input_v, pos_emb, x, xv);

    for (int i = 0; i < LL; i++) {
        const float* Wqi = Wq + (size_t)i * DD * DD;
        const float* Wki = Wk + (size_t)i * DD * DD;
        const float* Wvi = Wv + (size_t)i * DD * DD;
        const float* Woi = Wo + (size_t)i * DD * DD;
        const float* W1i = W1 + (size_t)i * DD * DFF;
        const float* W2i = W2 + (size_t)i * (DFF / 2) * (DD / 2);

        // QKV projections
        gemm128_kernel<<<dim3(DD / GN, M / GM), 256>>>(x,  Wqi, bq + i * DD, q, M, DD, DD, 0);
        gemm128_kernel<<<dim3(DD / GN, M / GM), 256>>>(x,  Wki, bk + i * DD, k, M, DD, DD, 0);
        gemm128_kernel<<<dim3(DD / GN, M / GM), 256>>>(xv, Wvi, bv + i * DD, v, M, DD, DD, 0);

        // attention
        attn_kernel<<<dim3(NN / 16, HH, BB), 256>>>(q, k, v, mask, ao, (i % 2) ? 1 : 0);

        // output projection
        gemm128_kernel<<<dim3(DD / GN, M / GM), 256>>>(ao, Woi, bo + i * DD, o, M, DD, DD, 0);

        // x = LN(x + o)
        ln_kernel<<<M, 256>>>(x, o, g1 + i * DD, be1 + i * DD, x);

        // FFN1 + GELU
        gemm128_kernel<<<dim3(DFF / GN, M / GM), 256>>>(x, W1i, b1 + i * DFF, h, M, DD, DFF, 1);

        // FFN2 grouped: (B*N*2, 512) @ (512, 128) -> contiguous (B*N, 256)
        gemm128_kernel<<<dim3((DD / 2) / GN, (2 * M) / GM), 256>>>(
            h, W2i, b2 + i * (DD / 2), h2, 2 * M, DFF / 2, DD / 2, 0);

        // x = LN(x + h2)
        ln_kernel<<<M, 256>>>(x, h2, g2 + i * DD, be2 + i * DD, x);
    }

    // final LN -> output
    ln_kernel<<<M, 256>>>(x, nullptr, gf, bf, (float*)d_out);
}